// round 12
// baseline (speedup 1.0000x reference)
#include <cuda_runtime.h>
#include <cuda_bf16.h>
#include <cfloat>
#include <cstdint>

// LossFun: loss = -sum over (b,l) of [argmax_v(scores)==target] * w * log(max score) / B
// scores: [B, L, V] float32, targets: [B, L] int32. B=8, L=2048, V=32000.
//
// PERSISTENT variant: grid = 152 SMs x 8 resident CTAs = 1216 CTAs, each
// grid-striding over ~13-14 rows. Removes the 13 wave transitions of the
// 16384-CTA launch (model: ~2360 cyc each -> ~17us of scheduler dead time);
// the load stream stays continuous across row boundaries.
//
// Scan (unchanged, measured 92-94% DRAM active): FMNMX-tree fast path,
// rare index-resolution slow path on running-best improvement only.
// Strict '>' + in-order resolution preserves argmax first-index tiebreak.
//
// Finalize stays a separate 1-thread kernel (in-kernel fusions measured
// -7..-10us WORSE in R6/R9). Precision: accurate logf + double accumulator
// (picked ~ 1-3e-5 -> log ~ -3e-5; __logf would be ~3e-3 relative error).

static constexpr int V_DIM  = 32000;
static constexpr double INV_B = 1.0 / 8.0;
static constexpr float  BETA  = 2.0f;
static constexpr int GRID_CTAS = 152 * 8;   // persistent grid

__device__ double g_acc;   // zero-init at module load; finalize resets per replay

__device__ __forceinline__ void tile_update(const float4& v, int base,
                                            int& bidx, float m)
{
    if (v.x == m && base + 0 < bidx) { bidx = base + 0; return; }
    if (v.y == m && base + 1 < bidx) { bidx = base + 1; return; }
    if (v.z == m && base + 2 < bidx) { bidx = base + 2; return; }
    if (v.w == m && base + 3 < bidx) { bidx = base + 3; return; }
}

__global__ __launch_bounds__(256, 4)
void lossfun_argmax_kernel(const float* __restrict__ scores,
                           const int* __restrict__ targets,
                           int rows)
{
    const int tid  = threadIdx.x;
    const int lane = tid & 31;
    const int wid  = tid >> 5;

    __shared__ float sv[8];
    __shared__ int   si[8];

    for (int row = blockIdx.x; row < rows; row += GRID_CTAS) {
        const float4* __restrict__ p =
            reinterpret_cast<const float4*>(scores + (size_t)row * V_DIM);

        float best = -FLT_MAX;
        int   bidx = 0x7FFFFFFF;

        // Main loop: 7 iterations x 4 coalesced float4 loads = 7168 vec4.
        #pragma unroll
        for (int k = 0; k < 7; k++) {
            const int i = tid + k * 1024;
            float4 a = __ldg(p + i);
            float4 b = __ldg(p + i + 256);
            float4 c = __ldg(p + i + 512);
            float4 d = __ldg(p + i + 768);

            float ma = fmaxf(fmaxf(a.x, a.y), fmaxf(a.z, a.w));
            float mb = fmaxf(fmaxf(b.x, b.y), fmaxf(b.z, b.w));
            float mc = fmaxf(fmaxf(c.x, c.y), fmaxf(c.z, c.w));
            float md = fmaxf(fmaxf(d.x, d.y), fmaxf(d.z, d.w));
            float m  = fmaxf(fmaxf(ma, mb), fmaxf(mc, md));

            if (m > best) {             // rare: ~ln(#tiles) per thread
                best = m;
                bidx = 0x7FFFFFFF;
                if      (ma == m) tile_update(a, (i)          << 2, bidx, m);
                if (bidx == 0x7FFFFFFF && mb == m) tile_update(b, (i + 256) << 2, bidx, m);
                if (bidx == 0x7FFFFFFF && mc == m) tile_update(c, (i + 512) << 2, bidx, m);
                if (bidx == 0x7FFFFFFF && md == m) tile_update(d, (i + 768) << 2, bidx, m);
            }
        }

        // Epilogue: vec4 indices 7168..7999 (832 = 3*256 + 64).
        {
            const int i1 = 7168 + tid;
            const int i2 = 7424 + tid;
            const int i3 = 7680 + tid;
            float4 a = __ldg(p + i1);
            float4 b = __ldg(p + i2);
            float4 c = __ldg(p + i3);

            float ma = fmaxf(fmaxf(a.x, a.y), fmaxf(a.z, a.w));
            float mb = fmaxf(fmaxf(b.x, b.y), fmaxf(b.z, b.w));
            float mc = fmaxf(fmaxf(c.x, c.y), fmaxf(c.z, c.w));
            float m  = fmaxf(fmaxf(ma, mb), mc);

            if (m > best) {
                best = m;
                bidx = 0x7FFFFFFF;
                if      (ma == m) tile_update(a, i1 << 2, bidx, m);
                if (bidx == 0x7FFFFFFF && mb == m) tile_update(b, i2 << 2, bidx, m);
                if (bidx == 0x7FFFFFFF && mc == m) tile_update(c, i3 << 2, bidx, m);
            }

            if (tid < 64) {
                const int i4 = 7936 + tid;
                float4 d = __ldg(p + i4);
                float md = fmaxf(fmaxf(d.x, d.y), fmaxf(d.z, d.w));
                if (md > best) {
                    best = md;
                    bidx = 0x7FFFFFFF;
                    tile_update(d, i4 << 2, bidx, md);
                }
            }
        }

        // Warp reduce (value-max, lowest index on tie)
        #pragma unroll
        for (int o = 16; o > 0; o >>= 1) {
            float ov = __shfl_down_sync(0xFFFFFFFFu, best, o);
            int   oi = __shfl_down_sync(0xFFFFFFFFu, bidx, o);
            if (ov > best || (ov == best && oi < bidx)) { best = ov; bidx = oi; }
        }

        if (lane == 0) { sv[wid] = best; si[wid] = bidx; }
        __syncthreads();

        if (tid == 0) {
            float fb = sv[0]; int fi = si[0];
            #pragma unroll
            for (int w = 1; w < 8; w++) {
                float ov = sv[w]; int oi = si[w];
                if (ov > fb || (ov == fb && oi < fi)) { fb = ov; fi = oi; }
            }
            int tgt = __ldg(targets + row);
            if (fi == tgt) {
                float w = (tgt == 0) ? 1.0f : BETA;
                atomicAdd(&g_acc, (double)(-w * logf(fb)));
            }
        }
        __syncthreads();   // protect sv/si reuse on the next row
    }
}

__global__ void lossfun_finalize_kernel(float* __restrict__ out)
{
    out[0] = (float)(g_acc * INV_B);
    g_acc  = 0.0;   // restore invariant for next graph replay
}

extern "C" void kernel_launch(void* const* d_in, const int* in_sizes, int n_in,
                              void* d_out, int out_size)
{
    const float* scores  = (const float*)d_in[0];
    const int*   targets = (const int*)d_in[1];
    float*       out     = (float*)d_out;

    const int rows = in_sizes[1];   // B * L = 16384
    const int grid = (rows < GRID_CTAS) ? rows : GRID_CTAS;

    lossfun_argmax_kernel<<<grid, 256>>>(scores, targets, rows);
    lossfun_finalize_kernel<<<1, 1>>>(out);
}

// round 13
// speedup vs baseline: 1.0857x; 1.0857x over previous
#include <cuda_runtime.h>
#include <cuda_bf16.h>
#include <cfloat>
#include <cstdint>

// LossFun: loss = -sum over (b,l) of [argmax_v(scores)==target] * w * log(max score) / B
// scores: [B, L, V] float32, targets: [B, L] int32. B=8, L=2048, V=32000.
//
// FINAL (best measured 283.1us, mean ~286 within +/-4us noise). Structure:
// one CTA per row streaming argmax (7.4-7.5 TB/s = 92-94% of HBM spec) +
// double g_acc atomic per matched row + 1-thread finalize kernel writing
// out and resetting g_acc (graph-replay determinism).
//
// Measured dead ends (12 rounds of evidence, do not revisit):
//  - last-CTA fusion w/ __threadfence (R6): +7.5us (MEMBAR drains the
//    saturated load stream);
//  - last-CTA fusion w/ atom.add.acq_rel counter (R9): +10us (tail
//    serialization on one L2 line);
//  - float atomic straight to d_out + memset node (R8): parity at best,
//    less precision margin;
//  - persistent 1216-CTA grid-stride (R12): +25us (per-row reduction +
//    barrier serializes the load stream at every row boundary; the HW
//    scheduler's work-stealing already hides wave transitions for
//    independent CTAs).
//
// Scan: FMNMX-tree fast path (tile max via single-instruction fmaxf, ~1.5
// instrs/float), rare index-resolution slow path only on running-best
// improvement (~ln(#tiles) per thread). Strict '>' update + in-order
// resolution preserves argmax first-index tiebreak.
//
// Precision: picked = max of 32000 uniforms ~ (1 - 3e-5), log(picked) ~ -3e-5:
// accurate logf (NOT __logf: ~1e-7 absolute error near 1 is ~3e-3 relative
// to a -3e-5 result) + double accumulator -> rel_err 2.3e-7.

static constexpr int V_DIM  = 32000;
static constexpr double INV_B = 1.0 / 8.0;
static constexpr float  BETA  = 2.0f;

__device__ double g_acc;   // zero-init at module load; finalize resets per replay

__device__ __forceinline__ void tile_update(const float4& v, int base,
                                            int& bidx, float m)
{
    if (v.x == m && base + 0 < bidx) { bidx = base + 0; return; }
    if (v.y == m && base + 1 < bidx) { bidx = base + 1; return; }
    if (v.z == m && base + 2 < bidx) { bidx = base + 2; return; }
    if (v.w == m && base + 3 < bidx) { bidx = base + 3; return; }
}

__global__ __launch_bounds__(256, 4)
void lossfun_argmax_kernel(const float* __restrict__ scores,
                           const int* __restrict__ targets)
{
    const int tid = threadIdx.x;
    const int row = blockIdx.x;
    const float4* __restrict__ p =
        reinterpret_cast<const float4*>(scores + (size_t)row * V_DIM);

    float best = -FLT_MAX;
    int   bidx = 0x7FFFFFFF;

    // Main loop: 7 iterations x 4 coalesced float4 loads = 7168 vec4.
    #pragma unroll
    for (int k = 0; k < 7; k++) {
        const int i = tid + k * 1024;
        float4 a = __ldg(p + i);
        float4 b = __ldg(p + i + 256);
        float4 c = __ldg(p + i + 512);
        float4 d = __ldg(p + i + 768);

        float ma = fmaxf(fmaxf(a.x, a.y), fmaxf(a.z, a.w));
        float mb = fmaxf(fmaxf(b.x, b.y), fmaxf(b.z, b.w));
        float mc = fmaxf(fmaxf(c.x, c.y), fmaxf(c.z, c.w));
        float md = fmaxf(fmaxf(d.x, d.y), fmaxf(d.z, d.w));
        float m  = fmaxf(fmaxf(ma, mb), fmaxf(mc, md));

        if (m > best) {                 // rare: ~ln(#tiles) per thread
            best = m;
            bidx = 0x7FFFFFFF;
            if      (ma == m) tile_update(a, (i)          << 2, bidx, m);
            if (bidx == 0x7FFFFFFF && mb == m) tile_update(b, (i + 256) << 2, bidx, m);
            if (bidx == 0x7FFFFFFF && mc == m) tile_update(c, (i + 512) << 2, bidx, m);
            if (bidx == 0x7FFFFFFF && md == m) tile_update(d, (i + 768) << 2, bidx, m);
        }
    }

    // Epilogue: vec4 indices 7168..7999 (832 = 3*256 + 64).
    {
        const int i1 = 7168 + tid;
        const int i2 = 7424 + tid;
        const int i3 = 7680 + tid;
        float4 a = __ldg(p + i1);
        float4 b = __ldg(p + i2);
        float4 c = __ldg(p + i3);

        float ma = fmaxf(fmaxf(a.x, a.y), fmaxf(a.z, a.w));
        float mb = fmaxf(fmaxf(b.x, b.y), fmaxf(b.z, b.w));
        float mc = fmaxf(fmaxf(c.x, c.y), fmaxf(c.z, c.w));
        float m  = fmaxf(fmaxf(ma, mb), mc);

        if (m > best) {
            best = m;
            bidx = 0x7FFFFFFF;
            if      (ma == m) tile_update(a, i1 << 2, bidx, m);
            if (bidx == 0x7FFFFFFF && mb == m) tile_update(b, i2 << 2, bidx, m);
            if (bidx == 0x7FFFFFFF && mc == m) tile_update(c, i3 << 2, bidx, m);
        }

        if (tid < 64) {
            const int i4 = 7936 + tid;
            float4 d = __ldg(p + i4);
            float md = fmaxf(fmaxf(d.x, d.y), fmaxf(d.z, d.w));
            if (md > best) {
                best = md;
                bidx = 0x7FFFFFFF;
                tile_update(d, i4 << 2, bidx, md);
            }
        }
    }

    // Warp reduce (value-max, lowest index on tie)
    #pragma unroll
    for (int o = 16; o > 0; o >>= 1) {
        float ov = __shfl_down_sync(0xFFFFFFFFu, best, o);
        int   oi = __shfl_down_sync(0xFFFFFFFFu, bidx, o);
        if (ov > best || (ov == best && oi < bidx)) { best = ov; bidx = oi; }
    }

    __shared__ float sv[8];
    __shared__ int   si[8];
    const int lane = tid & 31;
    const int wid  = tid >> 5;
    if (lane == 0) { sv[wid] = best; si[wid] = bidx; }
    __syncthreads();

    if (tid == 0) {
        float fb = sv[0]; int fi = si[0];
        #pragma unroll
        for (int w = 1; w < 8; w++) {
            float ov = sv[w]; int oi = si[w];
            if (ov > fb || (ov == fb && oi < fi)) { fb = ov; fi = oi; }
        }
        int tgt = __ldg(targets + row);
        if (fi == tgt) {
            float w = (tgt == 0) ? 1.0f : BETA;
            atomicAdd(&g_acc, (double)(-w * logf(fb)));
        }
    }
}

__global__ void lossfun_finalize_kernel(float* __restrict__ out)
{
    out[0] = (float)(g_acc * INV_B);
    g_acc  = 0.0;   // restore invariant for next graph replay
}

extern "C" void kernel_launch(void* const* d_in, const int* in_sizes, int n_in,
                              void* d_out, int out_size)
{
    const float* scores  = (const float*)d_in[0];
    const int*   targets = (const int*)d_in[1];
    float*       out     = (float*)d_out;

    const int rows = in_sizes[1];   // B * L = 16384

    lossfun_argmax_kernel<<<rows, 256>>>(scores, targets);
    lossfun_finalize_kernel<<<1, 1>>>(out);
}